// round 4
// baseline (speedup 1.0000x reference)
#include <cuda_runtime.h>
#include <math.h>

#define BB 4
#define LL 4096
#define DD 1024
#define NC 32            // chunks
#define LC (LL / NC)     // 128 steps per chunk

// scratch: per (b, chunk, d) complex state. 4*32*1024*8B = 1 MB
__device__ float2 g_scratch[BB * NC * DD];

__device__ __forceinline__ float2 cmul(float2 a, float2 b) {
    return make_float2(fmaf(a.x, b.x, -a.y * b.y), fmaf(a.x, b.y, a.y * b.x));
}

// phazor = p_raw/|p_raw| * exp(-|p_raw|)
__device__ __forceinline__ float2 get_phazor(const float* __restrict__ pr,
                                             const float* __restrict__ pi, int d) {
    float r = pr[d], i = pi[d];
    float mag = sqrtf(fmaf(r, r, i * i));
    float s = expf(-mag) / mag;
    return make_float2(r * s, i * s);
}

// -------- pass 1: per-chunk local recurrence (zero init) --------
__global__ void __launch_bounds__(256) pass1_kernel(const float* __restrict__ x,
                                                    const float* __restrict__ pr,
                                                    const float* __restrict__ pi) {
    int d = blockIdx.x * blockDim.x + threadIdx.x;   // 0..1023
    int c = blockIdx.y;                              // chunk
    int b = blockIdx.z;                              // batch

    float2 p = get_phazor(pr, pi, d);
    const float* xp = x + ((size_t)b * LL + (size_t)c * LC) * DD + d;

    float2 S = make_float2(0.f, 0.f);
#pragma unroll 1
    for (int i = 0; i < LC; i += 8) {
        float xs[8];
#pragma unroll
        for (int j = 0; j < 8; j++) xs[j] = xp[(size_t)(i + j) * DD];
#pragma unroll
        for (int j = 0; j < 8; j++) {
            float nr = fmaf(p.x, S.x, fmaf(-p.y, S.y, xs[j]));
            float ni = fmaf(p.x, S.y, p.y * S.x);
            S.x = nr; S.y = ni;
        }
    }
    g_scratch[((size_t)b * NC + c) * DD + d] = S;
}

// -------- pass 2: sequential combine across chunks; scratch becomes incoming states --------
__global__ void __launch_bounds__(256) pass2_kernel(const float* __restrict__ pr,
                                                    const float* __restrict__ pi) {
    int idx = blockIdx.x * blockDim.x + threadIdx.x; // 0..4095
    int d = idx & (DD - 1);
    int b = idx / DD;

    float2 p = get_phazor(pr, pi, d);
    float2 A = p;
#pragma unroll
    for (int k = 0; k < 7; k++) A = cmul(A, A);      // p^128 = p^LC

    float2 loc[NC];
#pragma unroll
    for (int c = 0; c < NC; c++) loc[c] = g_scratch[((size_t)b * NC + c) * DD + d];

    float2 S = make_float2(0.f, 0.f);
#pragma unroll
    for (int c = 0; c < NC; c++) {
        g_scratch[((size_t)b * NC + c) * DD + d] = S;  // incoming state for chunk c
        float nr = fmaf(A.x, S.x, fmaf(-A.y, S.y, loc[c].x));
        float ni = fmaf(A.x, S.y, fmaf(A.y, S.x, loc[c].y));
        S.x = nr; S.y = ni;
    }
}

// -------- pass 3: recompute with true incoming state, write output --------
// CPLX=true  : out is interleaved float pairs (re,im), indexed as float2.
// CPLX=false : out is real-part only, float stride = DD.
template <bool CPLX>
__global__ void __launch_bounds__(256) pass3_kernel(const float* __restrict__ x,
                                                    const float* __restrict__ hr,
                                                    const float* __restrict__ hi,
                                                    const float* __restrict__ pr,
                                                    const float* __restrict__ pi,
                                                    const float* __restrict__ ir_,
                                                    const float* __restrict__ ii_,
                                                    float* __restrict__ out) {
    int d = blockIdx.x * blockDim.x + threadIdx.x;
    int c = blockIdx.y;
    int b = blockIdx.z;

    float2 p = get_phazor(pr, pi, d);

    // pc = p^(c*LC + 1) via A = p^LC, Ae = A^c (binary pow; c uniform per block)
    float2 A = p;
#pragma unroll
    for (int k = 0; k < 7; k++) A = cmul(A, A);
    float2 Ae = make_float2(1.f, 0.f);
    float2 base = A;
    int e = c;
    while (e) {
        if (e & 1) Ae = cmul(Ae, base);
        base = cmul(base, base);
        e >>= 1;
    }
    float2 pc = cmul(p, Ae);                          // p^(c*LC+1)

    float2 h = make_float2(hr[(size_t)b * DD + d], hi[(size_t)b * DD + d]);
    float2 hp = cmul(h, pc);                          // hidden * p^(t+1) at t = c*LC
    float2 init = make_float2(ir_[d], ii_[d]);

    float2 S = g_scratch[((size_t)b * NC + c) * DD + d];

    size_t elem0 = ((size_t)b * LL + (size_t)c * LC) * DD + d;
    const float* xp = x + elem0;

#pragma unroll 1
    for (int i = 0; i < LC; i += 8) {
        float xs[8];
#pragma unroll
        for (int j = 0; j < 8; j++) xs[j] = xp[(size_t)(i + j) * DD];
#pragma unroll
        for (int j = 0; j < 8; j++) {
            float nr = fmaf(p.x, S.x, fmaf(-p.y, S.y, xs[j]));
            float ni = fmaf(p.x, S.y, p.y * S.x);
            S.x = nr; S.y = ni;
            float2 o;
            o.x = fmaf(init.x, S.x, fmaf(-init.y, S.y, hp.x));
            o.y = fmaf(init.x, S.y, fmaf(init.y, S.x, hp.y));
            size_t idx = elem0 + (size_t)(i + j) * DD;
            if (CPLX) {
                reinterpret_cast<float2*>(out)[idx] = o;
            } else {
                out[idx] = o.x;
            }
            // hp *= p
            float hr2 = fmaf(hp.x, p.x, -hp.y * p.y);
            float hi2 = fmaf(hp.x, p.y, hp.y * p.x);
            hp.x = hr2; hp.y = hi2;
        }
    }
}

extern "C" void kernel_launch(void* const* d_in, const int* in_sizes, int n_in,
                              void* d_out, int out_size) {
    const long long X_SZ = (long long)BB * LL * DD;  // 16,777,216
    const long long H_SZ = (long long)BB * DD;       // 4096
    const long long P_SZ = DD;                       // 1024

    // ---- locate x; detect element- vs byte-counted sizes ----
    int ix = -1;
    long long scale = 1;
    for (int i = 0; i < n_in; i++)
        if ((long long)in_sizes[i] == X_SZ) { ix = i; scale = 1; break; }
    if (ix < 0)
        for (int i = 0; i < n_in; i++)
            if ((long long)in_sizes[i] == X_SZ * 4) { ix = i; scale = 4; break; }

    const float *x, *hr, *hi, *pr, *pi, *ir_, *ii_;
    bool mapped = false;

    if (ix >= 0 && ix == n_in - 1 && n_in == 7) {
        // Alphabetical ordering: hidden_i, hidden_r, phazor_i, phazor_init_i,
        //                        phazor_init_r, phazor_r, x
        hi  = (const float*)d_in[0];
        hr  = (const float*)d_in[1];
        pi  = (const float*)d_in[2];
        ii_ = (const float*)d_in[3];
        ir_ = (const float*)d_in[4];
        pr  = (const float*)d_in[5];
        x   = (const float*)d_in[6];
        mapped = true;
    } else if (ix >= 0) {
        // Scan by size in appearance order (matches declared dict order).
        x = (const float*)d_in[ix];
        const float* h_list[2] = {0, 0};
        const float* p_list[4] = {0, 0, 0, 0};
        int nh = 0, np = 0;
        for (int i = 0; i < n_in; i++) {
            if (i == ix) continue;
            long long s = (long long)in_sizes[i];
            if (s == H_SZ * scale && nh < 2) h_list[nh++] = (const float*)d_in[i];
            else if (s == P_SZ * scale && np < 4) p_list[np++] = (const float*)d_in[i];
        }
        if (nh == 2 && np == 4) {
            hr  = h_list[0]; hi  = h_list[1];
            pr  = p_list[0]; pi  = p_list[1];
            ir_ = p_list[2]; ii_ = p_list[3];
            mapped = true;
        }
    }
    if (!mapped) {
        // Declared dict order fallback — never NULL pointers.
        x   = (const float*)d_in[0];
        hr  = (const float*)d_in[1];
        hi  = (const float*)d_in[2];
        pr  = (const float*)d_in[3];
        pi  = (const float*)d_in[4];
        ir_ = (const float*)d_in[5];
        ii_ = (const float*)d_in[6];
    }

    // ---- output layout from out_size (harness dtypes have no complex, so
    // complex64 must appear as 2x float32; a bare X_SZ count means real-only) ----
    long long osz = (long long)out_size;
    bool cplx;
    if (osz == 2 * X_SZ || osz == 8 * X_SZ)       cplx = true;   // interleaved (elems or bytes)
    else if (osz == X_SZ || osz == 4 * X_SZ)      cplx = false;  // real-only  (elems or bytes)
    else                                          cplx = true;   // default

    float* out = (float*)d_out;

    dim3 grid(DD / 256, NC, BB);
    pass1_kernel<<<grid, 256>>>(x, pr, pi);
    pass2_kernel<<<(BB * DD) / 256, 256>>>(pr, pi);
    if (cplx)
        pass3_kernel<true ><<<grid, 256>>>(x, hr, hi, pr, pi, ir_, ii_, out);
    else
        pass3_kernel<false><<<grid, 256>>>(x, hr, hi, pr, pi, ir_, ii_, out);
}